// round 17
// baseline (speedup 1.0000x reference)
#include <cuda_runtime.h>
#include <math.h>
#include <stdint.h>

// Problem constants
#define NTOK   65536
#define DIM    256
#define KCODE  1024
#define HW     1024
#define MT     64           // tokens per CTA
#define NC     64           // codes per B chunk
#define CHUNKS 16
#define MARGIN 8.0e-4f
#define NSLOT  8
#define APAD   132          // u32 (bf16x2) per A row (128 + 4 pad)
#define BPAD   132
#define BUFB   (NC*BPAD*4)  // 33792 bytes per B buffer

// smem byte offsets
#define OFF_A     0                             // 64*132*4 = 33792
#define OFF_B     33792                         // 2*33792 = 67584 -> 101376
#define OFF_CN    101376                        // 1024 f32 -> 105472
#define OFF_CANDV 105472                        // 64*8 f32 -> 107520
#define OFF_CANDI 107520                        // 64*8 i32 -> 109568
#define OFF_THR   109568                        // 64 u32 -> 109824
#define OFF_CNT   109824                        // 64 u32 -> 110080
#define OFF_XN    110080                        // 64 f32 -> 110336
#define OFF_SIDX  110336                        // 64 u32 -> 110592
#define OFF_RED   110592                        // 256 f32 -> 111616
#define SMEM_TOTAL 111616

__device__ __align__(16) float    g_cnorm[KCODE];
__device__ __align__(16) uint32_t g_cbf[KCODE * DIM / 2];   // bf16 codebook
__device__ int    g_idx[NTOK];
__device__ int    g_counts[KCODE];
__device__ double g_loss;

// ---------------- helpers ----------------
__device__ __forceinline__ uint32_t smem_u32(const void* p) {
    uint32_t a;
    asm("{ .reg .u64 t; cvta.to.shared.u64 t, %1; cvt.u32.u64 %0, t; }" : "=r"(a) : "l"(p));
    return a;
}
__device__ __forceinline__ uint32_t fkey(float f) {
    uint32_t u = __float_as_uint(f);
    return u ^ (uint32_t)(((int32_t)u >> 31) | 0x80000000);
}
__device__ __forceinline__ float fdec(uint32_t k) {
    uint32_t u = (k & 0x80000000u) ? (k ^ 0x80000000u) : ~k;
    return __uint_as_float(u);
}
__device__ __forceinline__ uint32_t packbf(float lo, float hi) {
    uint32_t r;
    asm("cvt.rn.bf16x2.f32 %0, %1, %2;" : "=r"(r) : "f"(hi), "f"(lo));
    return r;
}
__device__ __forceinline__ void mma_bf16(float* c, uint32_t a0, uint32_t a1,
                                         uint32_t a2, uint32_t a3,
                                         uint32_t b0, uint32_t b1) {
    asm volatile("mma.sync.aligned.m16n8k16.row.col.f32.bf16.bf16.f32 "
                 "{%0,%1,%2,%3}, {%4,%5,%6,%7}, {%8,%9}, {%0,%1,%2,%3};"
                 : "+f"(c[0]), "+f"(c[1]), "+f"(c[2]), "+f"(c[3])
                 : "r"(a0), "r"(a1), "r"(a2), "r"(a3), "r"(b0), "r"(b1));
}
__device__ __forceinline__ void cp_async16(uint32_t dst, const void* src) {
    asm volatile("cp.async.cg.shared.global [%0], [%1], 16;"
                 :: "r"(dst), "l"(__cvta_generic_to_global(src)) : "memory");
}
#define CP_COMMIT() asm volatile("cp.async.commit_group;" ::: "memory")
#define CP_WAIT1()  asm volatile("cp.async.wait_group 1;" ::: "memory")
#define CP_WAIT0()  asm volatile("cp.async.wait_group 0;" ::: "memory")

// ---------------------------------------------------------------------------
// Kernel A: sequential fp32 codebook norms (bit-identical chain order) +
// bf16 conversion + zeroing.  32 blocks x 32 threads (spread over 32 SMs).
// ---------------------------------------------------------------------------
__global__ void prep_kernel(const float* __restrict__ cb) {
    int gid = blockIdx.x * blockDim.x + threadIdx.x;
    if (gid < KCODE) {
        const float4* row = (const float4*)(cb + (size_t)gid * DIM);
        uint32_t* dst = g_cbf + (size_t)gid * (DIM / 2);
        float s = 0.f;
        for (int bq = 0; bq < 4; bq++) {
            float4 vb[16];
            #pragma unroll
            for (int q = 0; q < 16; q++) vb[q] = row[bq * 16 + q];
            #pragma unroll
            for (int q = 0; q < 16; q++) {
                float4 v = vb[q];
                s = __fadd_rn(s, __fmul_rn(v.x, v.x));
                s = __fadd_rn(s, __fmul_rn(v.y, v.y));
                s = __fadd_rn(s, __fmul_rn(v.z, v.z));
                s = __fadd_rn(s, __fmul_rn(v.w, v.w));
                int qq = bq * 16 + q;
                dst[2 * qq]     = packbf(v.x, v.y);
                dst[2 * qq + 1] = packbf(v.z, v.w);
            }
        }
        g_cnorm[gid] = s;
        g_counts[gid] = 0;
    }
    if (gid == 0) g_loss = 0.0;
}

// ---------------------------------------------------------------------------
// Main fused kernel: bf16 mma.sync + margin rings + exact fp32 rescue +
// argmin + histogram + loss + register-gather NCHW out.
// 1024 CTAs x 256 threads, 2 CTAs/SM.  Warp tile: m16 x n32 per chunk.
// ---------------------------------------------------------------------------
__global__ __launch_bounds__(256, 2)
void argmin_kernel(const float* __restrict__ x, const float* __restrict__ cb,
                   float* __restrict__ out_idx_f, float* __restrict__ out_q) {
    extern __shared__ char smem[];
    uint32_t* Au    = (uint32_t*)(smem + OFF_A);
    uint32_t* Bu0   = (uint32_t*)(smem + OFF_B);
    float*    cnS   = (float*)(smem + OFF_CN);
    float*    candv = (float*)(smem + OFF_CANDV);
    int*      candi = (int*)(smem + OFF_CANDI);
    uint32_t* thrS  = (uint32_t*)(smem + OFF_THR);
    uint32_t* cntS  = (uint32_t*)(smem + OFF_CNT);
    float*    xnS   = (float*)(smem + OFF_XN);
    uint32_t* sidxS = (uint32_t*)(smem + OFF_SIDX);
    float*    redS  = (float*)(smem + OFF_RED);

    const uint32_t sbB = smem_u32(smem + OFF_B);

    const int tid  = threadIdx.x;
    const int lane = tid & 31;
    const int wid  = tid >> 5;
    const int g    = lane >> 2;
    const int t    = lane & 3;
    const int mg   = wid >> 1;       // m-group 0..3: rows [mg*16, mg*16+16)
    const int ng   = wid & 1;        // n-group 0..1: codes [ng*32, ng*32+32) in chunk

    const int t0   = blockIdx.x * MT;
    const int b    = t0 >> 10;
    const int tloc = t0 & (HW - 1);
    const float* xb = x + (size_t)b * DIM * HW + tloc;   // (d,m): xb[d*HW+m]
    float* ob = out_q + (size_t)b * DIM * HW + tloc;

    // ---- issue B chunk 0 cp.async (overlaps A pass): 2048 x 16B ----
    {
        #pragma unroll
        for (int it = 0; it < 8; it++) {
            int e = tid + 256 * it;               // 0..2047
            int n = e >> 5, s4 = e & 31;
            cp_async16(sbB + (uint32_t)(n * (BPAD * 4) + s4 * 16),
                       g_cbf + (size_t)n * (DIM / 2) + s4 * 4);
        }
        CP_COMMIT();
    }

    // ---- per-token init + codebook norms ----
    if (tid < MT) {
        thrS[tid] = 0xFF800000u;    // fkey(+inf)
        cntS[tid] = 0;
    }
    ((float4*)cnS)[tid] = ((const float4*)g_cnorm)[tid];

    // ---- A pass: exact sequential xn + bf16 A tile (token m = tid < 64) ----
    if (tid < MT) {
        const float* xp = xb + tid;
        float xn = 0.f, prev = 0.f;
        #pragma unroll 8
        for (int d = 0; d < DIM; d++) {
            float v = xp[(size_t)d * HW];
            xn = __fadd_rn(xn, __fmul_rn(v, v));
            if (d & 1) Au[tid * APAD + (d >> 1)] = packbf(prev, v);
            else prev = v;
        }
        xnS[tid] = xn;
    }
    __syncthreads();

    // ---- MMA setup ----
    uint32_t* Ap = Au + (mg * 16 + g) * APAD + t;
    const int rowbase = mg * 16 + g;              // thread rows: rowbase, rowbase+8

    float acc[4][4];
    float lmin0 = INFINITY, lmin1 = INFINITY;
    float rv0[4], rv1[4];
    int   ri0[4], ri1[4];
    int   rc0 = 0, rc1 = 0;

#define RING_PUSH(RV, RI, RC, LM, sval, nval)                      \
    do {                                                           \
        if ((sval) < (LM) + MARGIN) {                              \
            RV[3] = RV[2]; RI[3] = RI[2];                          \
            RV[2] = RV[1]; RI[2] = RI[1];                          \
            RV[1] = RV[0]; RI[1] = RI[0];                          \
            RV[0] = (sval); RI[0] = (nval); RC++;                  \
            if ((sval) < (LM)) (LM) = (sval);                      \
        }                                                          \
    } while (0)

    for (int c = 0; c < CHUNKS; c++) {
        // issue chunk c+1 into the other buffer
        if (c + 1 < CHUNKS) {
            const uint32_t base = sbB + (uint32_t)(((c + 1) & 1) * BUFB);
            const uint32_t* srcb = g_cbf + (size_t)(c + 1) * NC * (DIM / 2);
            #pragma unroll
            for (int it = 0; it < 8; it++) {
                int e = tid + 256 * it;
                int n = e >> 5, s4 = e & 31;
                cp_async16(base + (uint32_t)(n * (BPAD * 4) + s4 * 16),
                           srcb + (size_t)n * (DIM / 2) + s4 * 4);
            }
        }
        CP_COMMIT();
        if (c + 1 < CHUNKS) CP_WAIT1(); else CP_WAIT0();
        __syncthreads();                          // chunk c visible to all warps

        #pragma unroll
        for (int j = 0; j < 4; j++)
            #pragma unroll
            for (int e = 0; e < 4; e++) acc[j][e] = 0.f;

        // B rows for this warp: ng*32 + j*8 + g, j = 0..3
        uint32_t* Br = Bu0 + (c & 1) * (NC * BPAD) + (ng * 32 + g) * BPAD + t;

        #pragma unroll
        for (int ks = 0; ks < 16; ks++) {
            const int col = ks * 8;               // u32 column
            uint32_t a0 = Ap[col],     a1 = Ap[8 * APAD + col];
            uint32_t a2 = Ap[col + 4], a3 = Ap[8 * APAD + col + 4];
            uint32_t b0[4], b1[4];
            #pragma unroll
            for (int j = 0; j < 4; j++) {
                b0[j] = Br[j * 8 * BPAD + col];
                b1[j] = Br[j * 8 * BPAD + col + 4];
            }
            #pragma unroll
            for (int j = 0; j < 4; j++)
                mma_bf16(acc[j], a0, a1, a2, a3, b0[j], b1[j]);
        }

        // fold chunk scores into register rings
        const int cb0 = c * NC + ng * 32;
        #pragma unroll
        for (int j = 0; j < 4; j++) {
            int n0 = cb0 + j * 8 + 2 * t;
            float cn0 = cnS[n0], cn1 = cnS[n0 + 1];
            float s00 = fmaf(-2.f, acc[j][0], cn0);
            float s01 = fmaf(-2.f, acc[j][1], cn1);
            float s10 = fmaf(-2.f, acc[j][2], cn0);
            float s11 = fmaf(-2.f, acc[j][3], cn1);
            RING_PUSH(rv0, ri0, rc0, lmin0, s00, n0);
            RING_PUSH(rv0, ri0, rc0, lmin0, s01, n0 + 1);
            RING_PUSH(rv1, ri1, rc1, lmin1, s10, n0);
            RING_PUSH(rv1, ri1, rc1, lmin1, s11, n0 + 1);
        }
        __syncthreads();                          // all reads of buf c&1 done
    }

    // ---- merge: global per-row threshold ----
    atomicMin(&thrS[rowbase],     fkey(lmin0));
    atomicMin(&thrS[rowbase + 8], fkey(lmin1));
    __syncthreads();

    // ---- filter-write candidates within gmin+MARGIN to shared ----
#define FILTER_ROW(RV, RI, RC, ROW)                                          \
    do {                                                                     \
        float thr = fdec(thrS[ROW]) + MARGIN;                                \
        int k = (RC < 4) ? RC : 4;                                           \
        _Pragma("unroll")                                                    \
        for (int sl = 0; sl < 4; sl++) {                                     \
            if (sl < k && RV[sl] <= thr) {                                   \
                uint32_t old = atomicAdd(&cntS[ROW], 1u);                    \
                if (old < NSLOT) {                                           \
                    candv[(ROW) * NSLOT + old] = RV[sl];                     \
                    candi[(ROW) * NSLOT + old] = RI[sl];                     \
                }                                                            \
            }                                                                \
        }                                                                    \
    } while (0)
    FILTER_ROW(rv0, ri0, rc0, rowbase);
    FILTER_ROW(rv1, ri1, rc1, rowbase + 8);
    __syncthreads();

    // ---- final per-token selection + exact rescue (token m = tid < 64) ----
    float tok_loss = 0.f;
    if (tid < MT) {
        const int m = tid;
        const float xn = xnS[m];
        uint32_t nv = cntS[m]; if (nv > NSLOT) nv = NSLOT;
        int bei = 0;

        if (nv == 1) {
            bei = candi[m * NSLOT];
            tok_loss = __fadd_rn(xn, candv[m * NSLOT]);
        } else if (nv >= 2) {
            float bev = __int_as_float(0x7F800000);
            bei = 0x7fffffff;
            for (int base = 0; base < NSLOT; base += 4) {
                if (base >= (int)nv) break;
                bool val[4]; int nn[4];
                #pragma unroll
                for (int q = 0; q < 4; q++) {
                    int sl = base + q;
                    bool v = (sl < (int)nv);
                    val[q] = v;
                    nn[q] = v ? candi[m * NSLOT + sl] : 0;
                }
                const float* p0 = cb + (size_t)nn[0] * DIM;
                const float* p1 = cb + (size_t)nn[1] * DIM;
                const float* p2 = cb + (size_t)nn[2] * DIM;
                const float* p3 = cb + (size_t)nn[3] * DIM;
                float a0 = 0.f, a1 = 0.f, a2 = 0.f, a3 = 0.f;
                #pragma unroll 8
                for (int d = 0; d < DIM; d++) {
                    float a = xb[(size_t)d * HW + m];    // exact f32 x
                    a0 = __fmaf_rn(a, p0[d], a0);
                    a1 = __fmaf_rn(a, p1[d], a1);
                    a2 = __fmaf_rn(a, p2[d], a2);
                    a3 = __fmaf_rn(a, p3[d], a3);
                }
                float accs[4] = {a0, a1, a2, a3};
                #pragma unroll
                for (int q = 0; q < 4; q++) {
                    if (!val[q]) continue;
                    float cn = cnS[nn[q]];
                    float t1 = __fadd_rn(xn, cn);
                    float se = __fadd_rn(t1, __fmul_rn(-2.f, accs[q]));
                    if (se < bev || (se == bev && nn[q] < bei)) { bev = se; bei = nn[q]; }
                }
            }
            tok_loss = bev;
        }
        // nv == 0 impossible (the global-min achiever always survives)

        int gt = t0 + m;
        g_idx[gt] = bei;
        out_idx_f[gt] = (float)bei;
        atomicAdd(&g_counts[bei], 1);
        sidxS[m] = (uint32_t)bei;
    }

    // ---- block loss reduction ----
    redS[tid] = tok_loss;
    __syncthreads();
    #pragma unroll
    for (int s = 128; s > 0; s >>= 1) {
        if (tid < s) redS[tid] += redS[tid + s];
        __syncthreads();
    }
    if (tid == 0) atomicAdd(&g_loss, (double)redS[0]);

    // ---- fused gather: 4 threads per token, register-only.
    // thread: token m = tid>>2, dims [part*64, part*64+64), part = tid&3.
    // Stores coalesce to 32B sectors per lane-group; codebook loads L2-hot.
    {
        const int m    = tid >> 2;
        const int part = tid & 3;
        const float4* src = (const float4*)(cb + (size_t)sidxS[m] * DIM + part * 64);
        float4 v[16];
        #pragma unroll
        for (int q = 0; q < 16; q++) v[q] = src[q];
        const float* vf = (const float*)v;
        #pragma unroll
        for (int j = 0; j < 64; j++) {
            ob[(size_t)(part * 64 + j) * HW + m] = vf[j];
        }
    }
}

// ---------------------------------------------------------------------------
// Finalize: loss + perplexity
// ---------------------------------------------------------------------------
__global__ void finalize_kernel(float* __restrict__ out_loss,
                                float* __restrict__ out_perp) {
    __shared__ float sred[KCODE];
    int t = threadIdx.x;
    float p = (float)g_counts[t] / (float)NTOK;
    sred[t] = p * logf(p + 1e-10f);
    __syncthreads();
    #pragma unroll
    for (int s = 512; s > 0; s >>= 1) {
        if (t < s) sred[t] += sred[t + s];
        __syncthreads();
    }
    if (t == 0) {
        out_perp[0] = expf(-sred[0]);
        out_loss[0] = (float)(1.25 * g_loss / ((double)NTOK * (double)DIM));
    }
}

// ---------------------------------------------------------------------------
extern "C" void kernel_launch(void* const* d_in, const int* in_sizes, int n_in,
                              void* d_out, int out_size) {
    const float* x  = (const float*)d_in[0];
    const float* cb = (const float*)d_in[1];
    if (n_in >= 2 && in_sizes[0] < in_sizes[1]) {
        const float* t = x; x = cb; cb = t;
    }

    float* out      = (float*)d_out;
    float* out_loss = out;
    float* out_q    = out + 1;
    float* out_perp = out + 1 + (size_t)NTOK * DIM;
    float* out_idx  = out + 2 + (size_t)NTOK * DIM;

    static int attr_done = 0;
    if (!attr_done) {
        cudaFuncSetAttribute(argmin_kernel, cudaFuncAttributeMaxDynamicSharedMemorySize, SMEM_TOTAL);
        attr_done = 1;
    }

    prep_kernel   <<<32, 32>>>(cb);
    argmin_kernel <<<NTOK / MT, 256, SMEM_TOTAL>>>(x, cb, out_idx, out_q);
    finalize_kernel<<<1, KCODE>>>(out_loss, out_perp);
}